// round 12
// baseline (speedup 1.0000x reference)
#include <cuda_runtime.h>
#include <cuda_bf16.h>
#include <math.h>
#include <stdint.h>

#define BATCH 4
#define DIMC  256
#define DI    256
#define NS    16
#define NPT   4096
#define NC    64
#define CL    64

// ---- mma.sync + cp.async helpers ----
__device__ __forceinline__ uint32_t smem_u32(const void* p) {
    uint32_t a; asm("{ .reg .u64 t; cvta.to.shared.u64 t, %1; cvt.u32.u64 %0, t; }" : "=r"(a) : "l"(p));
    return a;
}
__device__ __forceinline__ void mma_bf16(float* c, const uint32_t* a, const uint32_t* b) {
    asm volatile(
        "mma.sync.aligned.m16n8k16.row.col.f32.bf16.bf16.f32 "
        "{%0,%1,%2,%3}, {%4,%5,%6,%7}, {%8,%9}, {%0,%1,%2,%3};"
        : "+f"(c[0]), "+f"(c[1]), "+f"(c[2]), "+f"(c[3])
        : "r"(a[0]), "r"(a[1]), "r"(a[2]), "r"(a[3]), "r"(b[0]), "r"(b[1]));
}
__device__ __forceinline__ void ldsm4(uint32_t* r, uint32_t addr) {
    asm volatile("ldmatrix.sync.aligned.m8n8.x4.shared.b16 {%0,%1,%2,%3}, [%4];"
        : "=r"(r[0]), "=r"(r[1]), "=r"(r[2]), "=r"(r[3]) : "r"(addr));
}
__device__ __forceinline__ void ldsm2(uint32_t* r, uint32_t addr) {
    asm volatile("ldmatrix.sync.aligned.m8n8.x2.shared.b16 {%0,%1}, [%2];"
        : "=r"(r[0]), "=r"(r[1]) : "r"(addr));
}
__device__ __forceinline__ void cpa16(uint32_t s, const void* g) {
    asm volatile("cp.async.cg.shared.global [%0], [%1], 16;"
        :: "r"(s), "l"(__cvta_generic_to_global(g)));
}
#define CPA_COMMIT() asm volatile("cp.async.commit_group;" ::: "memory")

// ---------------- scratch (device globals) ----------------
static __device__ float g_xp[BATCH*256*NPT];        // in_proj x1 half [b][d][n]
static __device__ float g_deltaT[BATCH*NPT*DI];
static __device__ float g_Bm[BATCH*NPT*NS];
static __device__ float g_Cm[BATCH*NPT*NS];
static __device__ float g_P[BATCH*NC*NS*DI];
static __device__ int   g_flag[BATCH*NC];
static __device__ float g_A[DI*NS];
static __device__ float g_aL[DI*NS];
static __device__ __nv_bfloat16 g_whi[512*256];
static __device__ __nv_bfloat16 g_wlo[512*256];
static __device__ __nv_bfloat16 g_wohi[256*256];
static __device__ __nv_bfloat16 g_wolo[256*256];
static __device__ __nv_bfloat16 g_wbchi[32*256];
static __device__ __nv_bfloat16 g_wbclo[32*256];
static __device__ __nv_bfloat16 g_xthi[BATCH*NPT*DIMC];  // [b][n][c]
static __device__ __nv_bfloat16 g_xtlo[BATCH*NPT*DIMC];
static __device__ __nv_bfloat16 g_xshi[BATCH*NPT*DI];    // silu(conv) [b][n][d]
static __device__ __nv_bfloat16 g_xslo[BATCH*NPT*DI];
static __device__ __nv_bfloat16 g_yhi[BATCH*NPT*DI];     // [b][n][d]
static __device__ __nv_bfloat16 g_ylo[BATCH*NPT*DI];

// ---------------- K-prep ------------------------------------------------------
__global__ void k_prep(const float* __restrict__ A_log, const float* __restrict__ w_in,
                       const float* __restrict__ w_out, const float* __restrict__ Bw,
                       const float* __restrict__ Cw, const float* __restrict__ x) {
    int blk = blockIdx.x, tid = threadIdx.x;
    if (blk < 512) {
        int i = blk*256 + tid;
        float v = w_in[i];
        __nv_bfloat16 hi = __float2bfloat16(v);
        g_whi[i] = hi;
        g_wlo[i] = __float2bfloat16(v - __bfloat162float(hi));
    } else if (blk < 768) {
        int i = (blk-512)*256 + tid;
        float v = w_out[i];
        __nv_bfloat16 hi = __float2bfloat16(v);
        g_wohi[i] = hi;
        g_wolo[i] = __float2bfloat16(v - __bfloat162float(hi));
    } else if (blk < 784) {
        int i = (blk-768)*256 + tid;
        if (i < DI*NS) {
            float al = A_log[i];
            g_A[i]  = -expf(al);
            g_aL[i] =  expf((float)CL * al);   // CL even
        }
        if (i < BATCH*NC) g_flag[i] = 0;       // reset lookback flags every launch
    } else if (blk < 816) {
        int i = (blk-784)*256 + tid;
        float v = (i < 4096) ? Bw[i] : Cw[i - 4096];
        __nv_bfloat16 hi = __float2bfloat16(v);
        g_wbchi[i] = hi;
        g_wbclo[i] = __float2bfloat16(v - __bfloat162float(hi));
    } else {
        __shared__ float s[32][33];
        int t = blk - 816;
        int b = t >> 10, rem = t & 1023;
        int ct = rem >> 7, nt = rem & 127;
        int c0 = ct*32, n0 = nt*32;
        int tx = tid & 31, ty = tid >> 5;
        #pragma unroll
        for (int i = 0; i < 32; i += 8)
            s[ty+i][tx] = x[((size_t)b*DIMC + c0+ty+i)*NPT + n0 + tx];
        __syncthreads();
        #pragma unroll
        for (int i = 0; i < 32; i += 8) {
            float v = s[tx][ty+i];
            __nv_bfloat16 hi = __float2bfloat16(v);
            size_t idx = ((size_t)b*NPT + n0+ty+i)*DIMC + c0 + tx;
            g_xthi[idx] = hi;
            g_xtlo[idx] = __float2bfloat16(v - __bfloat162float(hi));
        }
    }
}

// ---------------- K1: in_proj mma.sync, cp.async 2-stage pipeline -----------
#define SAS 40
#define ARR_B (128*SAS*2)
#define STG_B (4*ARR_B)
#define MMA_DSM (2*STG_B)
__global__ void __launch_bounds__(256) k_mma_in(const float* __restrict__ bias) {
    extern __shared__ char dsm[];
    uint32_t sb = smem_u32(dsm);
    int tid = threadIdx.x, lane = tid & 31, wid = tid >> 5;
    int wm = wid & 1, wn = wid >> 1;
    int nt = blockIdx.x, mt = blockIdx.y, b = blockIdx.z;
    int o0 = mt*128, n0 = nt*128;

    float acc[4][4][4];
    #pragma unroll
    for (int i = 0; i < 4; i++)
        #pragma unroll
        for (int j = 0; j < 4; j++)
            #pragma unroll
            for (int q = 0; q < 4; q++) acc[i][j][q] = 0.f;

    auto issue = [&](int k, int stg) {
        uint32_t sbase = sb + (uint32_t)stg*STG_B;
        int k0 = k*32;
        #pragma unroll
        for (int i = 0; i < 2; i++) {
            int idx = tid + i*256;
            int row = idx >> 2, seg = idx & 3;
            uint32_t so = (uint32_t)((row*SAS + seg*8)*2);
            size_t ga = (size_t)(o0 + row)*256 + k0 + seg*8;
            size_t gb = ((size_t)b*NPT + n0 + row)*DIMC + k0 + seg*8;
            cpa16(sbase + so,             &g_whi[ga]);
            cpa16(sbase + ARR_B + so,     &g_wlo[ga]);
            cpa16(sbase + 2*ARR_B + so,   &g_xthi[gb]);
            cpa16(sbase + 3*ARR_B + so,   &g_xtlo[gb]);
        }
        CPA_COMMIT();
    };

    uint32_t aoff = (uint32_t)(((wm*64 + (lane&15))*SAS + (lane>>4)*8) * 2);
    uint32_t boff = (uint32_t)(((wn*32 + (lane&7))*SAS + ((lane>>3)&1)*8) * 2);

    issue(0, 0);
    issue(1, 1);

    #pragma unroll
    for (int k = 0; k < 8; k++) {
        if (k < 7) asm volatile("cp.async.wait_group 1;" ::: "memory");
        else       asm volatile("cp.async.wait_group 0;" ::: "memory");
        __syncthreads();
        int stg = k & 1;
        uint32_t aBase = sb + (uint32_t)stg*STG_B + aoff;
        uint32_t bBase = sb + (uint32_t)stg*STG_B + 2*ARR_B + boff;
        #pragma unroll
        for (int ks = 0; ks < 2; ks++) {
            uint32_t koff = ks*32;
            uint32_t ah[4][4], al[4][4], bh[4][2], bl[4][2];
            #pragma unroll
            for (int mi = 0; mi < 4; mi++) {
                ldsm4(ah[mi], aBase + mi*(16*SAS*2) + koff);
                ldsm4(al[mi], aBase + ARR_B + mi*(16*SAS*2) + koff);
            }
            #pragma unroll
            for (int ni = 0; ni < 4; ni++) {
                ldsm2(bh[ni], bBase + ni*(8*SAS*2) + koff);
                ldsm2(bl[ni], bBase + ARR_B + ni*(8*SAS*2) + koff);
            }
            #pragma unroll
            for (int mi = 0; mi < 4; mi++)
                #pragma unroll
                for (int ni = 0; ni < 4; ni++) {
                    mma_bf16(acc[mi][ni], ah[mi], bh[ni]);
                    mma_bf16(acc[mi][ni], ah[mi], bl[ni]);
                    mma_bf16(acc[mi][ni], al[mi], bh[ni]);
                }
        }
        __syncthreads();
        if (k + 2 < 8) issue(k + 2, stg);
    }
    __syncthreads();

    if (mt < 2) {
        #pragma unroll
        for (int mi = 0; mi < 4; mi++) {
            int orow = o0 + wm*64 + mi*16 + (lane>>2);
            float bi0 = bias[orow], bi1 = bias[orow+8];
            #pragma unroll
            for (int ni = 0; ni < 4; ni++) {
                int col = n0 + wn*32 + ni*8 + (lane&3)*2;
                float* d0 = &g_xp[((size_t)b*256 + orow)*NPT + col];
                *(float2*)d0 = make_float2(acc[mi][ni][0] + bi0, acc[mi][ni][1] + bi0);
                *(float2*)(d0 + (size_t)8*NPT) =
                    make_float2(acc[mi][ni][2] + bi1, acc[mi][ni][3] + bi1);
            }
        }
    } else {
        float* stage = (float*)dsm;
        int d0base = (mt - 2) * 128;
        #pragma unroll
        for (int mi = 0; mi < 4; mi++) {
            int rl = wm*64 + mi*16 + (lane>>2);
            float bi0 = bias[o0 + rl], bi1 = bias[o0 + rl + 8];
            #pragma unroll
            for (int ni = 0; ni < 4; ni++) {
                int cl = wn*32 + ni*8 + (lane&3)*2;
                float v0 = acc[mi][ni][0] + bi0, v1 = acc[mi][ni][1] + bi0;
                float v2 = acc[mi][ni][2] + bi1, v3 = acc[mi][ni][3] + bi1;
                stage[(size_t)cl*132 + rl]         = __fdividef(1.f, 1.f + __expf(-v0));
                stage[(size_t)(cl+1)*132 + rl]     = __fdividef(1.f, 1.f + __expf(-v1));
                stage[(size_t)cl*132 + rl + 8]     = __fdividef(1.f, 1.f + __expf(-v2));
                stage[(size_t)(cl+1)*132 + rl + 8] = __fdividef(1.f, 1.f + __expf(-v3));
            }
        }
        __syncthreads();
        for (int idx = tid; idx < 128*128; idx += 256) {
            int n = idx >> 7, dl = idx & 127;
            g_deltaT[((size_t)b*NPT + n0 + n)*DI + d0base + dl] = stage[(size_t)n*132 + dl];
        }
    }
}

// ---------------- K2a: conv+silu -> xs hi/lo bf16 transposed ----------------
#define CZ_P1 133
__global__ void k_convz(const float* __restrict__ wconv, const float* __restrict__ bconv) {
    __shared__ float s1[32*CZ_P1];
    int b = blockIdx.z, dt = blockIdx.y, nt = blockIdx.x;
    int d0 = dt*32, n0 = nt*128;
    int tid = threadIdx.x;
    int tx = tid & 31, ty = tid >> 5;
    const float* xpb = g_xp + (size_t)b*256*NPT;

    for (int r = ty; r < 32; r += 8) {
        const float* src = &xpb[(size_t)(d0+r)*NPT + n0 - 3];
        for (int c = tx; c < 131; c += 32) {
            int n = n0 - 3 + c;
            s1[r*CZ_P1 + c] = (n >= 0) ? src[c] : 0.f;
        }
    }
    __syncthreads();

    int d = d0 + tx;
    float w0 = wconv[d*4+0], w1 = wconv[d*4+1], w2 = wconv[d*4+2], w3 = wconv[d*4+3];
    float bc = bconv[d];
    __nv_bfloat16* xh = g_xshi + ((size_t)b*NPT + n0)*DI + d;
    __nv_bfloat16* xl = g_xslo + ((size_t)b*NPT + n0)*DI + d;
    const float* r1 = &s1[tx*CZ_P1];
    #pragma unroll 4
    for (int n = ty; n < 128; n += 8) {
        float v = fmaf(w3, r1[n+3], fmaf(w2, r1[n+2], fmaf(w1, r1[n+1], fmaf(w0, r1[n], bc))));
        float sv = __fdividef(v, 1.f + __expf(-v));
        __nv_bfloat16 hi = __float2bfloat16(sv);
        xh[(size_t)n*DI] = hi;
        xl[(size_t)n*DI] = __float2bfloat16(sv - __bfloat162float(hi));
    }
}

// ---------------- K2b: B/C projection via mma.sync, 3-stage pipeline --------
#define BC_AB (64*SAS*2)
#define BC_BB (32*SAS*2)
#define BC_STG (2*BC_AB + 2*BC_BB)
__global__ void __launch_bounds__(256) k_mma_bc() {
    __shared__ __align__(16) char dsm[3*BC_STG];
    uint32_t sb = smem_u32(dsm);
    int tid = threadIdx.x, lane = tid & 31, wid = tid >> 5;
    int wm = wid & 3, wn = wid >> 2;
    size_t r0 = (size_t)blockIdx.x * 64;

    float acc[2][4];
    #pragma unroll
    for (int i = 0; i < 2; i++)
        #pragma unroll
        for (int q = 0; q < 4; q++) acc[i][q] = 0.f;

    auto issue = [&](int k, int stg) {
        uint32_t sbase = sb + (uint32_t)stg*BC_STG;
        int k0 = k*32;
        #pragma unroll
        for (int i = 0; i < 2; i++) {
            int idx = tid + i*256;
            int arr = idx >> 8, rem = idx & 255;
            int row = rem >> 2, seg = rem & 3;
            uint32_t so = (uint32_t)arr*BC_AB + (uint32_t)((row*SAS + seg*8)*2);
            size_t g = (r0 + row)*DI + k0 + seg*8;
            cpa16(sbase + so, arr ? (const void*)&g_xslo[g] : (const void*)&g_xshi[g]);
        }
        {
            int arr = tid >> 7, rem = tid & 127;
            int row = rem >> 2, seg = rem & 3;
            uint32_t so = 2*BC_AB + (uint32_t)arr*BC_BB + (uint32_t)((row*SAS + seg*8)*2);
            size_t g = (size_t)row*256 + k0 + seg*8;
            cpa16(sbase + so, arr ? (const void*)&g_wbclo[g] : (const void*)&g_wbchi[g]);
        }
        CPA_COMMIT();
    };

    uint32_t aoff = (uint32_t)(((wm*16 + (lane&15))*SAS + (lane>>4)*8) * 2);
    uint32_t boff = 2*BC_AB + (uint32_t)(((wn*16 + (lane&7))*SAS + ((lane>>3)&1)*8) * 2);

    issue(0, 0);
    issue(1, 1);
    issue(2, 2);

    #pragma unroll
    for (int k = 0; k < 8; k++) {
        if (k < 6)       asm volatile("cp.async.wait_group 2;" ::: "memory");
        else if (k == 6) asm volatile("cp.async.wait_group 1;" ::: "memory");
        else             asm volatile("cp.async.wait_group 0;" ::: "memory");
        __syncthreads();
        int stg = k % 3;
        uint32_t aBase = sb + (uint32_t)stg*BC_STG + aoff;
        uint32_t bBase = sb + (uint32_t)stg*BC_STG + boff;
        #pragma unroll
        for (int ks = 0; ks < 2; ks++) {
            uint32_t koff = ks*32;
            uint32_t ah[4], al[4], bh[2][2], bl[2][2];
            ldsm4(ah, aBase + koff);
            ldsm4(al, aBase + BC_AB + koff);
            #pragma unroll
            for (int ni = 0; ni < 2; ni++) {
                ldsm2(bh[ni], bBase + ni*(8*SAS*2) + koff);
                ldsm2(bl[ni], bBase + BC_BB + ni*(8*SAS*2) + koff);
            }
            #pragma unroll
            for (int ni = 0; ni < 2; ni++) {
                mma_bf16(acc[ni], ah, bh[ni]);
                mma_bf16(acc[ni], ah, bl[ni]);
                mma_bf16(acc[ni], al, bh[ni]);
            }
        }
        __syncthreads();
        if (k + 3 < 8) issue(k + 3, stg);
    }

    #pragma unroll
    for (int ni = 0; ni < 2; ni++) {
        int col = wn*16 + ni*8 + (lane&3)*2;
        float* base = (col < 16) ? g_Bm : g_Cm;
        int cb = col & 15;
        size_t row = r0 + wm*16 + (lane>>2);
        *(float2*)&base[row*NS + cb]     = make_float2(acc[ni][0], acc[ni][1]);
        *(float2*)&base[(row+8)*NS + cb] = make_float2(acc[ni][2], acc[ni][3]);
    }
}

// ---------------- K3: single-pass scan with decoupled lookback ---------------
// Pass1: local scan -> publish P + flag. Lookback: replay prefix from all
// predecessors' P (exact same fma order as the old scan2 -> bit-identical).
// Pass2: final scan from H0, write y hi/lo.
__global__ void __launch_bounds__(256) k_scan_fused(const float* __restrict__ Dskip) {
    __shared__ float sB[CL*NS], sC[CL*NS];
    int b = blockIdx.y, ch = blockIdx.x;
    int tid = threadIdx.x;                   // = d
    int t0 = ch * CL;
    for (int i = tid; i < CL*NS; i += 256) {
        sB[i] = g_Bm[((size_t)b*NPT + t0)*NS + i];
        sC[i] = g_Cm[((size_t)b*NPT + t0)*NS + i];
    }
    __syncthreads();

    float A[NS], h[NS];
    #pragma unroll
    for (int s = 0; s < NS; s++) { A[s] = g_A[tid*NS + s]; h[s] = 0.f; }
    const float* dptr = g_deltaT + ((size_t)b*NPT + t0)*DI + tid;

    // ---- pass 1: local scan (zero init) ----
    for (int k = 0; k < CL; k++) {
        float dl = dptr[(size_t)k*DI];
        const float* Bk = &sB[k*NS];
        #pragma unroll
        for (int s = 0; s < NS; s++)
            h[s] = fmaf(A[s], h[s], dl * Bk[s]);
    }
    // publish P + flag
    {
        float* P = g_P + ((size_t)b*NC + ch)*NS*DI + tid;
        #pragma unroll
        for (int s = 0; s < NS; s++) P[s*DI] = h[s];
        __threadfence();
        __syncthreads();
        if (tid == 0) atomicExch(&g_flag[b*NC + ch], 1);
    }

    // ---- lookback: H0 = prefix over chunks 0..ch-1 ----
    float h0[NS];
    #pragma unroll
    for (int s = 0; s < NS; s++) h0[s] = 0.f;
    if (ch > 0) {
        if (tid < ch)
            while (atomicAdd(&g_flag[b*NC + tid], 0) == 0) {}
        __threadfence();
        __syncthreads();
        float aL[NS];
        #pragma unroll
        for (int s = 0; s < NS; s++) aL[s] = g_aL[tid*NS + s];
        for (int c = 0; c < ch; c++) {
            const float* Pp = g_P + ((size_t)b*NC + c)*NS*DI + tid;
            #pragma unroll
            for (int s = 0; s < NS; s++)
                h0[s] = fmaf(aL[s], h0[s], Pp[s*DI]);
        }
    }

    // ---- pass 2: final scan with correct init, write y hi/lo ----
    #pragma unroll
    for (int s = 0; s < NS; s++) h[s] = h0[s];
    float dsk = Dskip[tid];
    const __nv_bfloat16* xhp = g_xshi + ((size_t)b*NPT + t0)*DI + tid;
    const __nv_bfloat16* xlp = g_xslo + ((size_t)b*NPT + t0)*DI + tid;
    __nv_bfloat16* yh = g_yhi + ((size_t)b*NPT + t0)*DI + tid;
    __nv_bfloat16* yl = g_ylo + ((size_t)b*NPT + t0)*DI + tid;
    for (int k = 0; k < CL; k++) {
        float dl = dptr[(size_t)k*DI];
        float xv = __bfloat162float(xhp[(size_t)k*DI]) + __bfloat162float(xlp[(size_t)k*DI]);
        const float* Bk = &sB[k*NS];
        const float* Ck = &sC[k*NS];
        float y = dsk * xv;
        #pragma unroll
        for (int s = 0; s < NS; s++) {
            h[s] = fmaf(A[s], h[s], dl * Bk[s]);
            y = fmaf(h[s], Ck[s], y);
        }
        __nv_bfloat16 hi = __float2bfloat16(y);
        yh[(size_t)k*DI] = hi;
        yl[(size_t)k*DI] = __float2bfloat16(y - __bfloat162float(hi));
    }
}

// ---------------- K6: fused out_proj + bias + residual + LN + store ----------
#define OL_A_B (128*SAS*2)
#define OL_B_B (256*SAS*2)
#define OL_STG (2*OL_A_B + 2*OL_B_B)
#define OL_DSM (2*OL_STG)
__global__ void __launch_bounds__(512) k_mma_out_ln(
    const float* __restrict__ x, const float* __restrict__ bout,
    const float* __restrict__ gamma, const float* __restrict__ beta,
    float* __restrict__ out) {
    extern __shared__ char dsm[];
    uint32_t sb = smem_u32(dsm);
    int tid = threadIdx.x, lane = tid & 31, wid = tid >> 5;
    int wm = wid & 3, wn = wid >> 2;
    size_t r0 = (size_t)blockIdx.x * 128;
    int b = (int)(r0 >> 12);
    int n0 = (int)(r0 & 4095);

    float acc[2][8][4];
    #pragma unroll
    for (int i = 0; i < 2; i++)
        #pragma unroll
        for (int j = 0; j < 8; j++)
            #pragma unroll
            for (int q = 0; q < 4; q++) acc[i][j][q] = 0.f;

    auto issue = [&](int k, int stg) {
        uint32_t sbase = sb + (uint32_t)stg*OL_STG;
        int k0 = k*32;
        #pragma unroll
        for (int i = 0; i < 2; i++) {
            int idx = tid + i*512;
            int arr = idx >> 9, rem = idx & 511;
            int row = rem >> 2, seg = rem & 3;
            uint32_t so = (uint32_t)arr*OL_A_B + (uint32_t)((row*SAS + seg*8)*2);
            size_t g = (r0 + row)*DI + k0 + seg*8;
            cpa16(sbase + so, arr ? (const void*)&g_ylo[g] : (const void*)&g_yhi[g]);
        }
        #pragma unroll
        for (int i = 0; i < 4; i++) {
            int idx = tid + i*512;
            int arr = idx >> 10, rem = idx & 1023;
            int row = rem >> 2, seg = rem & 3;
            uint32_t so = 2*OL_A_B + (uint32_t)arr*OL_B_B + (uint32_t)((row*SAS + seg*8)*2);
            size_t g = (size_t)row*DI + k0 + seg*8;
            cpa16(sbase + so, arr ? (const void*)&g_wolo[g] : (const void*)&g_wohi[g]);
        }
        CPA_COMMIT();
    };

    uint32_t aoff = (uint32_t)(((wm*32 + (lane&15))*SAS + (lane>>4)*8) * 2);
    uint32_t boff = 2*OL_A_B + (uint32_t)(((wn*64 + (lane&7))*SAS + ((lane>>3)&1)*8) * 2);

    issue(0, 0);
    issue(1, 1);

    #pragma unroll
    for (int k = 0; k < 8; k++) {
        if (k < 7) asm volatile("cp.async.wait_group 1;" ::: "memory");
        else       asm volatile("cp.async.wait_group 0;" ::: "memory");
        __syncthreads();
        int stg = k & 1;
        uint32_t aBase = sb + (uint32_t)stg*OL_STG + aoff;
        uint32_t bBase = sb + (uint32_t)stg*OL_STG + boff;
        #pragma unroll
        for (int ks = 0; ks < 2; ks++) {
            uint32_t koff = ks*32;
            uint32_t ah[2][4], al[2][4], bh[8][2], bl[8][2];
            #pragma unroll
            for (int mi = 0; mi < 2; mi++) {
                ldsm4(ah[mi], aBase + mi*(16*SAS*2) + koff);
                ldsm4(al[mi], aBase + OL_A_B + mi*(16*SAS*2) + koff);
            }
            #pragma unroll
            for (int ni = 0; ni < 8; ni++) {
                ldsm2(bh[ni], bBase + ni*(8*SAS*2) + koff);
                ldsm2(bl[ni], bBase + OL_B_B + ni*(8*SAS*2) + koff);
            }
            #pragma unroll
            for (int mi = 0; mi < 2; mi++)
                #pragma unroll
                for (int ni = 0; ni < 8; ni++) {
                    mma_bf16(acc[mi][ni], ah[mi], bh[ni]);
                    mma_bf16(acc[mi][ni], ah[mi], bl[ni]);
                    mma_bf16(acc[mi][ni], al[mi], bh[ni]);
                }
        }
        __syncthreads();
        if (k + 2 < 8) issue(k + 2, stg);
    }
    __syncthreads();

    float* stage = (float*)dsm;
    float* mu = (float*)(dsm + 256*36*4);
    float* rs = mu + 32;
    for (int p = 0; p < 4; p++) {
        if (wm == p) {
            #pragma unroll
            for (int mi = 0; mi < 2; mi++) {
                int rl = mi*16 + (lane>>2);
                #pragma unroll
                for (int ni = 0; ni < 8; ni++) {
                    int c = wn*64 + ni*8 + (lane&3)*2;
                    float b0 = bout[c], b1 = bout[c+1];
                    stage[(size_t)c*36 + rl]         = acc[mi][ni][0] + b0;
                    stage[(size_t)(c+1)*36 + rl]     = acc[mi][ni][1] + b1;
                    stage[(size_t)c*36 + rl + 8]     = acc[mi][ni][2] + b0;
                    stage[(size_t)(c+1)*36 + rl + 8] = acc[mi][ni][3] + b1;
                }
            }
        }
        __syncthreads();
        int nb = n0 + p*32;
        for (int idx = tid; idx < 8192; idx += 512) {
            int c = idx >> 5, nn = idx & 31;
            stage[(size_t)c*36 + nn] += x[((size_t)b*DIMC + c)*NPT + nb + nn];
        }
        __syncthreads();
        {
            int nn = wid*2 + (lane>>4);
            int h = lane & 15;
            float sum = 0.f, sq = 0.f;
            #pragma unroll
            for (int c = h; c < 256; c += 16) {
                float v = stage[(size_t)c*36 + nn];
                sum += v; sq += v*v;
            }
            #pragma unroll
            for (int o = 1; o < 16; o <<= 1) {
                sum += __shfl_xor_sync(0xFFFFFFFFu, sum, o);
                sq  += __shfl_xor_sync(0xFFFFFFFFu, sq,  o);
            }
            if (h == 0) {
                float m = sum * (1.f/256.f);
                mu[nn] = m;
                rs[nn] = rsqrtf(sq * (1.f/256.f) - m*m + 1e-5f);
            }
        }
        __syncthreads();
        for (int idx = tid; idx < 8192; idx += 512) {
            int c = idx >> 5, nn = idx & 31;
            float v = (stage[(size_t)c*36 + nn] - mu[nn]) * rs[nn] * gamma[c] + beta[c];
            out[((size_t)b*DIMC + c)*NPT + nb + nn] = v;
        }
        __syncthreads();
    }
}

// ---------------- launch ------------------------------------------------------
extern "C" void kernel_launch(void* const* d_in, const int* in_sizes, int n_in,
                              void* d_out, int out_size) {
    const float* x      = (const float*)d_in[0];
    const float* w_in   = (const float*)d_in[1];
    const float* b_in   = (const float*)d_in[2];
    const float* w_conv = (const float*)d_in[3];
    const float* b_conv = (const float*)d_in[4];
    const float* A_log  = (const float*)d_in[5];
    const float* D_skip = (const float*)d_in[6];
    const float* Bw     = (const float*)d_in[7];
    const float* Cw     = (const float*)d_in[8];
    const float* w_out  = (const float*)d_in[9];
    const float* b_out  = (const float*)d_in[10];
    const float* gamma  = (const float*)d_in[11];
    const float* beta   = (const float*)d_in[12];
    float* out = (float*)d_out;

    cudaFuncSetAttribute(k_mma_in,     cudaFuncAttributeMaxDynamicSharedMemorySize, MMA_DSM);
    cudaFuncSetAttribute(k_mma_out_ln, cudaFuncAttributeMaxDynamicSharedMemorySize, OL_DSM);

    k_prep<<<816 + 4096, 256>>>(A_log, w_in, w_out, Bw, Cw, x);
    k_mma_in<<<dim3(32, 4, BATCH), 256, MMA_DSM>>>(b_in);
    k_convz<<<dim3(32, 8, BATCH), 256>>>(w_conv, b_conv);
    k_mma_bc<<<256, 256>>>();
    k_scan_fused<<<dim3(NC, BATCH), 256>>>(D_skip);
    k_mma_out_ln<<<128, 512, OL_DSM>>>(x, b_out, gamma, beta, out);
}

// round 13
// speedup vs baseline: 1.0755x; 1.0755x over previous
#include <cuda_runtime.h>
#include <cuda_bf16.h>
#include <math.h>
#include <stdint.h>

#define BATCH 4
#define DIMC  256
#define DI    256
#define NS    16
#define NPT   4096
#define NC    64
#define CL    64

// ---- mma.sync + cp.async helpers ----
__device__ __forceinline__ uint32_t smem_u32(const void* p) {
    uint32_t a; asm("{ .reg .u64 t; cvta.to.shared.u64 t, %1; cvt.u32.u64 %0, t; }" : "=r"(a) : "l"(p));
    return a;
}
__device__ __forceinline__ void mma_bf16(float* c, const uint32_t* a, const uint32_t* b) {
    asm volatile(
        "mma.sync.aligned.m16n8k16.row.col.f32.bf16.bf16.f32 "
        "{%0,%1,%2,%3}, {%4,%5,%6,%7}, {%8,%9}, {%0,%1,%2,%3};"
        : "+f"(c[0]), "+f"(c[1]), "+f"(c[2]), "+f"(c[3])
        : "r"(a[0]), "r"(a[1]), "r"(a[2]), "r"(a[3]), "r"(b[0]), "r"(b[1]));
}
__device__ __forceinline__ void ldsm4(uint32_t* r, uint32_t addr) {
    asm volatile("ldmatrix.sync.aligned.m8n8.x4.shared.b16 {%0,%1,%2,%3}, [%4];"
        : "=r"(r[0]), "=r"(r[1]), "=r"(r[2]), "=r"(r[3]) : "r"(addr));
}
__device__ __forceinline__ void ldsm2(uint32_t* r, uint32_t addr) {
    asm volatile("ldmatrix.sync.aligned.m8n8.x2.shared.b16 {%0,%1}, [%2];"
        : "=r"(r[0]), "=r"(r[1]) : "r"(addr));
}
__device__ __forceinline__ void cpa16(uint32_t s, const void* g) {
    asm volatile("cp.async.cg.shared.global [%0], [%1], 16;"
        :: "r"(s), "l"(__cvta_generic_to_global(g)));
}
#define CPA_COMMIT() asm volatile("cp.async.commit_group;" ::: "memory")

// ---------------- scratch (device globals) ----------------
static __device__ float g_xp[BATCH*256*NPT];        // in_proj x1 half [b][d][n]
static __device__ float g_deltaT[BATCH*NPT*DI];
static __device__ float g_Bm[BATCH*NPT*NS];
static __device__ float g_Cm[BATCH*NPT*NS];
static __device__ float g_P[BATCH*NC*NS*DI];
static __device__ float g_H0[BATCH*NC*NS*DI];
static __device__ float g_A[DI*NS];
static __device__ float g_aL[DI*NS];
static __device__ __nv_bfloat16 g_whi[512*256];
static __device__ __nv_bfloat16 g_wlo[512*256];
static __device__ __nv_bfloat16 g_wohi[256*256];
static __device__ __nv_bfloat16 g_wolo[256*256];
static __device__ __nv_bfloat16 g_wbchi[32*256];
static __device__ __nv_bfloat16 g_wbclo[32*256];
static __device__ __nv_bfloat16 g_xthi[BATCH*NPT*DIMC];  // [b][n][c]
static __device__ __nv_bfloat16 g_xtlo[BATCH*NPT*DIMC];
static __device__ __nv_bfloat16 g_xshi[BATCH*NPT*DI];    // silu(conv) [b][n][d]
static __device__ __nv_bfloat16 g_xslo[BATCH*NPT*DI];
static __device__ __nv_bfloat16 g_yhi[BATCH*NPT*DI];     // [b][n][d]
static __device__ __nv_bfloat16 g_ylo[BATCH*NPT*DI];

// ---------------- K-prep ------------------------------------------------------
__global__ void k_prep(const float* __restrict__ A_log, const float* __restrict__ w_in,
                       const float* __restrict__ w_out, const float* __restrict__ Bw,
                       const float* __restrict__ Cw, const float* __restrict__ x) {
    int blk = blockIdx.x, tid = threadIdx.x;
    if (blk < 512) {
        int i = blk*256 + tid;
        float v = w_in[i];
        __nv_bfloat16 hi = __float2bfloat16(v);
        g_whi[i] = hi;
        g_wlo[i] = __float2bfloat16(v - __bfloat162float(hi));
    } else if (blk < 768) {
        int i = (blk-512)*256 + tid;
        float v = w_out[i];
        __nv_bfloat16 hi = __float2bfloat16(v);
        g_wohi[i] = hi;
        g_wolo[i] = __float2bfloat16(v - __bfloat162float(hi));
    } else if (blk < 784) {
        int i = (blk-768)*256 + tid;
        if (i < DI*NS) {
            float al = A_log[i];
            g_A[i]  = -expf(al);
            g_aL[i] =  expf((float)CL * al);   // CL even
        }
    } else if (blk < 816) {
        int i = (blk-784)*256 + tid;
        float v = (i < 4096) ? Bw[i] : Cw[i - 4096];
        __nv_bfloat16 hi = __float2bfloat16(v);
        g_wbchi[i] = hi;
        g_wbclo[i] = __float2bfloat16(v - __bfloat162float(hi));
    } else {
        __shared__ float s[32][33];
        int t = blk - 816;
        int b = t >> 10, rem = t & 1023;
        int ct = rem >> 7, nt = rem & 127;
        int c0 = ct*32, n0 = nt*32;
        int tx = tid & 31, ty = tid >> 5;
        #pragma unroll
        for (int i = 0; i < 32; i += 8)
            s[ty+i][tx] = x[((size_t)b*DIMC + c0+ty+i)*NPT + n0 + tx];
        __syncthreads();
        #pragma unroll
        for (int i = 0; i < 32; i += 8) {
            float v = s[tx][ty+i];
            __nv_bfloat16 hi = __float2bfloat16(v);
            size_t idx = ((size_t)b*NPT + n0+ty+i)*DIMC + c0 + tx;
            g_xthi[idx] = hi;
            g_xtlo[idx] = __float2bfloat16(v - __bfloat162float(hi));
        }
    }
}

// ---------------- K1: in_proj mma.sync, cp.async 2-stage pipeline -----------
#define SAS 40
#define ARR_B (128*SAS*2)
#define STG_B (4*ARR_B)
#define MMA_DSM (2*STG_B)
__global__ void __launch_bounds__(256) k_mma_in(const float* __restrict__ bias) {
    extern __shared__ char dsm[];
    uint32_t sb = smem_u32(dsm);
    int tid = threadIdx.x, lane = tid & 31, wid = tid >> 5;
    int wm = wid & 1, wn = wid >> 1;
    int nt = blockIdx.x, mt = blockIdx.y, b = blockIdx.z;
    int o0 = mt*128, n0 = nt*128;

    float acc[4][4][4];
    #pragma unroll
    for (int i = 0; i < 4; i++)
        #pragma unroll
        for (int j = 0; j < 4; j++)
            #pragma unroll
            for (int q = 0; q < 4; q++) acc[i][j][q] = 0.f;

    auto issue = [&](int k, int stg) {
        uint32_t sbase = sb + (uint32_t)stg*STG_B;
        int k0 = k*32;
        #pragma unroll
        for (int i = 0; i < 2; i++) {
            int idx = tid + i*256;
            int row = idx >> 2, seg = idx & 3;
            uint32_t so = (uint32_t)((row*SAS + seg*8)*2);
            size_t ga = (size_t)(o0 + row)*256 + k0 + seg*8;
            size_t gb = ((size_t)b*NPT + n0 + row)*DIMC + k0 + seg*8;
            cpa16(sbase + so,             &g_whi[ga]);
            cpa16(sbase + ARR_B + so,     &g_wlo[ga]);
            cpa16(sbase + 2*ARR_B + so,   &g_xthi[gb]);
            cpa16(sbase + 3*ARR_B + so,   &g_xtlo[gb]);
        }
        CPA_COMMIT();
    };

    uint32_t aoff = (uint32_t)(((wm*64 + (lane&15))*SAS + (lane>>4)*8) * 2);
    uint32_t boff = (uint32_t)(((wn*32 + (lane&7))*SAS + ((lane>>3)&1)*8) * 2);

    issue(0, 0);
    issue(1, 1);

    #pragma unroll
    for (int k = 0; k < 8; k++) {
        if (k < 7) asm volatile("cp.async.wait_group 1;" ::: "memory");
        else       asm volatile("cp.async.wait_group 0;" ::: "memory");
        __syncthreads();
        int stg = k & 1;
        uint32_t aBase = sb + (uint32_t)stg*STG_B + aoff;
        uint32_t bBase = sb + (uint32_t)stg*STG_B + 2*ARR_B + boff;
        #pragma unroll
        for (int ks = 0; ks < 2; ks++) {
            uint32_t koff = ks*32;
            uint32_t ah[4][4], al[4][4], bh[4][2], bl[4][2];
            #pragma unroll
            for (int mi = 0; mi < 4; mi++) {
                ldsm4(ah[mi], aBase + mi*(16*SAS*2) + koff);
                ldsm4(al[mi], aBase + ARR_B + mi*(16*SAS*2) + koff);
            }
            #pragma unroll
            for (int ni = 0; ni < 4; ni++) {
                ldsm2(bh[ni], bBase + ni*(8*SAS*2) + koff);
                ldsm2(bl[ni], bBase + ARR_B + ni*(8*SAS*2) + koff);
            }
            #pragma unroll
            for (int mi = 0; mi < 4; mi++)
                #pragma unroll
                for (int ni = 0; ni < 4; ni++) {
                    mma_bf16(acc[mi][ni], ah[mi], bh[ni]);
                    mma_bf16(acc[mi][ni], ah[mi], bl[ni]);
                    mma_bf16(acc[mi][ni], al[mi], bh[ni]);
                }
        }
        __syncthreads();
        if (k + 2 < 8) issue(k + 2, stg);
    }
    __syncthreads();

    if (mt < 2) {
        #pragma unroll
        for (int mi = 0; mi < 4; mi++) {
            int orow = o0 + wm*64 + mi*16 + (lane>>2);
            float bi0 = bias[orow], bi1 = bias[orow+8];
            #pragma unroll
            for (int ni = 0; ni < 4; ni++) {
                int col = n0 + wn*32 + ni*8 + (lane&3)*2;
                float* d0 = &g_xp[((size_t)b*256 + orow)*NPT + col];
                *(float2*)d0 = make_float2(acc[mi][ni][0] + bi0, acc[mi][ni][1] + bi0);
                *(float2*)(d0 + (size_t)8*NPT) =
                    make_float2(acc[mi][ni][2] + bi1, acc[mi][ni][3] + bi1);
            }
        }
    } else {
        float* stage = (float*)dsm;
        int d0base = (mt - 2) * 128;
        #pragma unroll
        for (int mi = 0; mi < 4; mi++) {
            int rl = wm*64 + mi*16 + (lane>>2);
            float bi0 = bias[o0 + rl], bi1 = bias[o0 + rl + 8];
            #pragma unroll
            for (int ni = 0; ni < 4; ni++) {
                int cl = wn*32 + ni*8 + (lane&3)*2;
                float v0 = acc[mi][ni][0] + bi0, v1 = acc[mi][ni][1] + bi0;
                float v2 = acc[mi][ni][2] + bi1, v3 = acc[mi][ni][3] + bi1;
                stage[(size_t)cl*132 + rl]         = __fdividef(1.f, 1.f + __expf(-v0));
                stage[(size_t)(cl+1)*132 + rl]     = __fdividef(1.f, 1.f + __expf(-v1));
                stage[(size_t)cl*132 + rl + 8]     = __fdividef(1.f, 1.f + __expf(-v2));
                stage[(size_t)(cl+1)*132 + rl + 8] = __fdividef(1.f, 1.f + __expf(-v3));
            }
        }
        __syncthreads();
        for (int idx = tid; idx < 128*128; idx += 256) {
            int n = idx >> 7, dl = idx & 127;
            g_deltaT[((size_t)b*NPT + n0 + n)*DI + d0base + dl] = stage[(size_t)n*132 + dl];
        }
    }
}

// ---------------- K2a: conv+silu -> xs hi/lo bf16 transposed ----------------
#define CZ_P1 133
__global__ void k_convz(const float* __restrict__ wconv, const float* __restrict__ bconv) {
    __shared__ float s1[32*CZ_P1];
    int b = blockIdx.z, dt = blockIdx.y, nt = blockIdx.x;
    int d0 = dt*32, n0 = nt*128;
    int tid = threadIdx.x;
    int tx = tid & 31, ty = tid >> 5;
    const float* xpb = g_xp + (size_t)b*256*NPT;

    for (int r = ty; r < 32; r += 8) {
        const float* src = &xpb[(size_t)(d0+r)*NPT + n0 - 3];
        for (int c = tx; c < 131; c += 32) {
            int n = n0 - 3 + c;
            s1[r*CZ_P1 + c] = (n >= 0) ? src[c] : 0.f;
        }
    }
    __syncthreads();

    int d = d0 + tx;
    float w0 = wconv[d*4+0], w1 = wconv[d*4+1], w2 = wconv[d*4+2], w3 = wconv[d*4+3];
    float bc = bconv[d];
    __nv_bfloat16* xh = g_xshi + ((size_t)b*NPT + n0)*DI + d;
    __nv_bfloat16* xl = g_xslo + ((size_t)b*NPT + n0)*DI + d;
    const float* r1 = &s1[tx*CZ_P1];
    #pragma unroll 4
    for (int n = ty; n < 128; n += 8) {
        float v = fmaf(w3, r1[n+3], fmaf(w2, r1[n+2], fmaf(w1, r1[n+1], fmaf(w0, r1[n], bc))));
        float sv = __fdividef(v, 1.f + __expf(-v));
        __nv_bfloat16 hi = __float2bfloat16(sv);
        xh[(size_t)n*DI] = hi;
        xl[(size_t)n*DI] = __float2bfloat16(sv - __bfloat162float(hi));
    }
}

// ---------------- K2b: B/C projection via mma.sync, 3-stage pipeline --------
#define BC_AB (64*SAS*2)
#define BC_BB (32*SAS*2)
#define BC_STG (2*BC_AB + 2*BC_BB)
__global__ void __launch_bounds__(256) k_mma_bc() {
    __shared__ __align__(16) char dsm[3*BC_STG];
    uint32_t sb = smem_u32(dsm);
    int tid = threadIdx.x, lane = tid & 31, wid = tid >> 5;
    int wm = wid & 3, wn = wid >> 2;
    size_t r0 = (size_t)blockIdx.x * 64;

    float acc[2][4];
    #pragma unroll
    for (int i = 0; i < 2; i++)
        #pragma unroll
        for (int q = 0; q < 4; q++) acc[i][q] = 0.f;

    auto issue = [&](int k, int stg) {
        uint32_t sbase = sb + (uint32_t)stg*BC_STG;
        int k0 = k*32;
        #pragma unroll
        for (int i = 0; i < 2; i++) {
            int idx = tid + i*256;
            int arr = idx >> 8, rem = idx & 255;
            int row = rem >> 2, seg = rem & 3;
            uint32_t so = (uint32_t)arr*BC_AB + (uint32_t)((row*SAS + seg*8)*2);
            size_t g = (r0 + row)*DI + k0 + seg*8;
            cpa16(sbase + so, arr ? (const void*)&g_xslo[g] : (const void*)&g_xshi[g]);
        }
        {
            int arr = tid >> 7, rem = tid & 127;
            int row = rem >> 2, seg = rem & 3;
            uint32_t so = 2*BC_AB + (uint32_t)arr*BC_BB + (uint32_t)((row*SAS + seg*8)*2);
            size_t g = (size_t)row*256 + k0 + seg*8;
            cpa16(sbase + so, arr ? (const void*)&g_wbclo[g] : (const void*)&g_wbchi[g]);
        }
        CPA_COMMIT();
    };

    uint32_t aoff = (uint32_t)(((wm*16 + (lane&15))*SAS + (lane>>4)*8) * 2);
    uint32_t boff = 2*BC_AB + (uint32_t)(((wn*16 + (lane&7))*SAS + ((lane>>3)&1)*8) * 2);

    issue(0, 0);
    issue(1, 1);
    issue(2, 2);

    #pragma unroll
    for (int k = 0; k < 8; k++) {
        if (k < 6)       asm volatile("cp.async.wait_group 2;" ::: "memory");
        else if (k == 6) asm volatile("cp.async.wait_group 1;" ::: "memory");
        else             asm volatile("cp.async.wait_group 0;" ::: "memory");
        __syncthreads();
        int stg = k % 3;
        uint32_t aBase = sb + (uint32_t)stg*BC_STG + aoff;
        uint32_t bBase = sb + (uint32_t)stg*BC_STG + boff;
        #pragma unroll
        for (int ks = 0; ks < 2; ks++) {
            uint32_t koff = ks*32;
            uint32_t ah[4], al[4], bh[2][2], bl[2][2];
            ldsm4(ah, aBase + koff);
            ldsm4(al, aBase + BC_AB + koff);
            #pragma unroll
            for (int ni = 0; ni < 2; ni++) {
                ldsm2(bh[ni], bBase + ni*(8*SAS*2) + koff);
                ldsm2(bl[ni], bBase + BC_BB + ni*(8*SAS*2) + koff);
            }
            #pragma unroll
            for (int ni = 0; ni < 2; ni++) {
                mma_bf16(acc[ni], ah, bh[ni]);
                mma_bf16(acc[ni], ah, bl[ni]);
                mma_bf16(acc[ni], al, bh[ni]);
            }
        }
        __syncthreads();
        if (k + 3 < 8) issue(k + 3, stg);
    }

    #pragma unroll
    for (int ni = 0; ni < 2; ni++) {
        int col = wn*16 + ni*8 + (lane&3)*2;
        float* base = (col < 16) ? g_Bm : g_Cm;
        int cb = col & 15;
        size_t row = r0 + wm*16 + (lane>>2);
        *(float2*)&base[row*NS + cb]     = make_float2(acc[ni][0], acc[ni][1]);
        *(float2*)&base[(row+8)*NS + cb] = make_float2(acc[ni][2], acc[ni][3]);
    }
}

// ---------------- K3 (S1): per-chunk local scan -> P ------------------------
__global__ void k_scan1() {
    __shared__ float sB[CL*NS];
    int b = blockIdx.y, ch = blockIdx.x;
    int tid = threadIdx.x;
    int t0 = ch * CL;
    for (int i = tid; i < CL*NS; i += 256)
        sB[i] = g_Bm[((size_t)b*NPT + t0)*NS + i];
    __syncthreads();
    float A[NS], h[NS];
    #pragma unroll
    for (int s = 0; s < NS; s++) { A[s] = g_A[tid*NS + s]; h[s] = 0.f; }
    const float* dptr = g_deltaT + ((size_t)b*NPT + t0)*DI + tid;
    for (int k = 0; k < CL; k++) {
        float dl = dptr[(size_t)k*DI];
        const float* Bk = &sB[k*NS];
        #pragma unroll
        for (int s = 0; s < NS; s++)
            h[s] = fmaf(A[s], h[s], dl * Bk[s]);
    }
    float* P = g_P + ((size_t)b*NC + ch)*NS*DI + tid;
    #pragma unroll
    for (int s = 0; s < NS; s++) P[s*DI] = h[s];
}

// ---------------- K4 (S2): inter-chunk prefix --------------------------------
__global__ void k_scan2() {
    int g = blockIdx.x * 256 + threadIdx.x;
    int d = g & 255;
    int s = (g >> 8) & 15;
    int b = g >> 12;
    float aL = g_aL[d*NS + s];
    float h = 0.f;
    size_t base = ((size_t)b*NC*NS + s)*DI + d;
    for (int c = 0; c < NC; c++) {
        size_t idx = base + (size_t)c*NS*DI;
        g_H0[idx] = h;
        h = fmaf(aL, h, g_P[idx]);
    }
}

// ---------------- K5 (S3): final scan + y hi/lo bf16 -------------------------
__global__ void k_scan3(const float* __restrict__ Dskip) {
    __shared__ float sB[CL*NS], sC[CL*NS];
    int b = blockIdx.y, ch = blockIdx.x;
    int tid = threadIdx.x;
    int t0 = ch * CL;
    for (int i = tid; i < CL*NS; i += 256) {
        sB[i] = g_Bm[((size_t)b*NPT + t0)*NS + i];
        sC[i] = g_Cm[((size_t)b*NPT + t0)*NS + i];
    }
    __syncthreads();
    float A[NS], h[NS];
    size_t hbase = ((size_t)b*NC + ch)*NS*DI + tid;
    #pragma unroll
    for (int s = 0; s < NS; s++) { A[s] = g_A[tid*NS + s]; h[s] = g_H0[hbase + s*DI]; }
    float dsk = Dskip[tid];
    const float* dptr = g_deltaT + ((size_t)b*NPT + t0)*DI + tid;
    const __nv_bfloat16* xhp = g_xshi + ((size_t)b*NPT + t0)*DI + tid;
    const __nv_bfloat16* xlp = g_xslo + ((size_t)b*NPT + t0)*DI + tid;
    __nv_bfloat16* yh = g_yhi + ((size_t)b*NPT + t0)*DI + tid;
    __nv_bfloat16* yl = g_ylo + ((size_t)b*NPT + t0)*DI + tid;
    for (int k = 0; k < CL; k++) {
        float dl = dptr[(size_t)k*DI];
        float xv = __bfloat162float(xhp[(size_t)k*DI]) + __bfloat162float(xlp[(size_t)k*DI]);
        const float* Bk = &sB[k*NS];
        const float* Ck = &sC[k*NS];
        float y = dsk * xv;
        #pragma unroll
        for (int s = 0; s < NS; s++) {
            h[s] = fmaf(A[s], h[s], dl * Bk[s]);
            y = fmaf(h[s], Ck[s], y);
        }
        __nv_bfloat16 hi = __float2bfloat16(y);
        yh[(size_t)k*DI] = hi;
        yl[(size_t)k*DI] = __float2bfloat16(y - __bfloat162float(hi));
    }
}

// ---------------- K6: fused out_proj + LN, 256 blocks x 64 rows --------------
#define OL_A_B (64*SAS*2)              // A array (64 rows)
#define OL_B_B (256*SAS*2)             // B array (256 rows)
#define OL_STG (2*OL_A_B + 2*OL_B_B)   // 51200
#define OL_DSM (2*OL_STG)              // 102400
__global__ void __launch_bounds__(512) k_mma_out_ln(
    const float* __restrict__ x, const float* __restrict__ bout,
    const float* __restrict__ gamma, const float* __restrict__ beta,
    float* __restrict__ out) {
    extern __shared__ char dsm[];
    uint32_t sb = smem_u32(dsm);
    int tid = threadIdx.x, lane = tid & 31, wid = tid >> 5;
    int wm = wid & 1, wn = wid >> 1;       // 2 m-groups (32 rows) x 8 n-groups (32 cols)
    size_t r0 = (size_t)blockIdx.x * 64;   // rows over (b,n)
    int b = (int)(r0 >> 12);
    int n0 = (int)(r0 & 4095);

    float acc[2][4][4];
    #pragma unroll
    for (int i = 0; i < 2; i++)
        #pragma unroll
        for (int j = 0; j < 4; j++)
            #pragma unroll
            for (int q = 0; q < 4; q++) acc[i][j][q] = 0.f;

    auto issue = [&](int k, int stg) {
        uint32_t sbase = sb + (uint32_t)stg*OL_STG;
        int k0 = k*32;
        {   // A: yhi/ylo, 512 cp -> 1 per thread
            int arr = tid >> 8, rem = tid & 255;
            int row = rem >> 2, seg = rem & 3;
            uint32_t so = (uint32_t)arr*OL_A_B + (uint32_t)((row*SAS + seg*8)*2);
            size_t g = (r0 + row)*DI + k0 + seg*8;
            cpa16(sbase + so, arr ? (const void*)&g_ylo[g] : (const void*)&g_yhi[g]);
        }
        #pragma unroll
        for (int i = 0; i < 4; i++) {   // B: wohi/wolo, 2048 cp -> 4 per thread
            int idx = tid + i*512;
            int arr = idx >> 10, rem = idx & 1023;
            int row = rem >> 2, seg = rem & 3;
            uint32_t so = 2*OL_A_B + (uint32_t)arr*OL_B_B + (uint32_t)((row*SAS + seg*8)*2);
            size_t g = (size_t)row*DI + k0 + seg*8;
            cpa16(sbase + so, arr ? (const void*)&g_wolo[g] : (const void*)&g_wohi[g]);
        }
        CPA_COMMIT();
    };

    uint32_t aoff = (uint32_t)(((wm*32 + (lane&15))*SAS + (lane>>4)*8) * 2);
    uint32_t boff = 2*OL_A_B + (uint32_t)(((wn*32 + (lane&7))*SAS + ((lane>>3)&1)*8) * 2);

    issue(0, 0);
    issue(1, 1);

    #pragma unroll
    for (int k = 0; k < 8; k++) {
        if (k < 7) asm volatile("cp.async.wait_group 1;" ::: "memory");
        else       asm volatile("cp.async.wait_group 0;" ::: "memory");
        __syncthreads();
        int stg = k & 1;
        uint32_t aBase = sb + (uint32_t)stg*OL_STG + aoff;
        uint32_t bBase = sb + (uint32_t)stg*OL_STG + boff;
        #pragma unroll
        for (int ks = 0; ks < 2; ks++) {
            uint32_t koff = ks*32;
            uint32_t ah[2][4], al[2][4], bh[4][2], bl[4][2];
            #pragma unroll
            for (int mi = 0; mi < 2; mi++) {
                ldsm4(ah[mi], aBase + mi*(16*SAS*2) + koff);
                ldsm4(al[mi], aBase + OL_A_B + mi*(16*SAS*2) + koff);
            }
            #pragma unroll
            for (int ni = 0; ni < 4; ni++) {
                ldsm2(bh[ni], bBase + ni*(8*SAS*2) + koff);
                ldsm2(bl[ni], bBase + OL_B_B + ni*(8*SAS*2) + koff);
            }
            #pragma unroll
            for (int mi = 0; mi < 2; mi++)
                #pragma unroll
                for (int ni = 0; ni < 4; ni++) {
                    mma_bf16(acc[mi][ni], ah[mi], bh[ni]);
                    mma_bf16(acc[mi][ni], ah[mi], bl[ni]);
                    mma_bf16(acc[mi][ni], al[mi], bh[ni]);
                }
        }
        __syncthreads();
        if (k + 2 < 8) issue(k + 2, stg);
    }
    __syncthreads();

    // ---- epilogue: 2 chunks of 32 rows; stage[c][nn] fp32, stride 36 ----
    float* stage = (float*)dsm;            // 256*36*4 = 36864 B
    float* mu = (float*)(dsm + 256*36*4);
    float* rs = mu + 32;
    for (int p = 0; p < 2; p++) {
        if (wm == p) {
            #pragma unroll
            for (int mi = 0; mi < 2; mi++) {
                int rl = mi*16 + (lane>>2);
                #pragma unroll
                for (int ni = 0; ni < 4; ni++) {
                    int c = wn*32 + ni*8 + (lane&3)*2;
                    float b0 = bout[c], b1 = bout[c+1];
                    stage[(size_t)c*36 + rl]         = acc[mi][ni][0] + b0;
                    stage[(size_t)(c+1)*36 + rl]     = acc[mi][ni][1] + b1;
                    stage[(size_t)c*36 + rl + 8]     = acc[mi][ni][2] + b0;
                    stage[(size_t)(c+1)*36 + rl + 8] = acc[mi][ni][3] + b1;
                }
            }
        }
        __syncthreads();
        int nb = n0 + p*32;
        for (int idx = tid; idx < 8192; idx += 512) {
            int c = idx >> 5, nn = idx & 31;
            stage[(size_t)c*36 + nn] += x[((size_t)b*DIMC + c)*NPT + nb + nn];
        }
        __syncthreads();
        {
            int nn = wid*2 + (lane>>4);
            int h = lane & 15;
            float sum = 0.f, sq = 0.f;
            #pragma unroll
            for (int c = h; c < 256; c += 16) {
                float v = stage[(size_t)c*36 + nn];
                sum += v; sq += v*v;
            }
            #pragma unroll
            for (int o = 1; o < 16; o <<= 1) {
                sum += __shfl_xor_sync(0xFFFFFFFFu, sum, o);
                sq  += __shfl_xor_sync(0xFFFFFFFFu, sq,  o);
            }
            if (h == 0) {
                float m = sum * (1.f/256.f);
                mu[nn] = m;
                rs[nn] = rsqrtf(sq * (1.f/256.f) - m*m + 1e-5f);
            }
        }
        __syncthreads();
        for (int idx = tid; idx < 8192; idx += 512) {
            int c = idx >> 5, nn = idx & 31;
            float v = (stage[(size_t)c*36 + nn] - mu[nn]) * rs[nn] * gamma[c] + beta[c];
            out[((size_t)b*DIMC + c)*NPT + nb + nn] = v;
        }
        __syncthreads();
    }
}

// ---------------- launch ------------------------------------------------------
extern "C" void kernel_launch(void* const* d_in, const int* in_sizes, int n_in,
                              void* d_out, int out_size) {
    const float* x      = (const float*)d_in[0];
    const float* w_in   = (const float*)d_in[1];
    const float* b_in   = (const float*)d_in[2];
    const float* w_conv = (const float*)d_in[3];
    const float* b_conv = (const float*)d_in[4];
    const float* A_log  = (const float*)d_in[5];
    const float* D_skip = (const float*)d_in[6];
    const float* Bw     = (const float*)d_in[7];
    const float* Cw     = (const float*)d_in[8];
    const float* w_out  = (const float*)d_in[9];
    const float* b_out  = (const float*)d_in[10];
    const float* gamma  = (const float*)d_in[11];
    const float* beta   = (const float*)d_in[12];
    float* out = (float*)d_out;

    cudaFuncSetAttribute(k_mma_in,     cudaFuncAttributeMaxDynamicSharedMemorySize, MMA_DSM);
    cudaFuncSetAttribute(k_mma_out_ln, cudaFuncAttributeMaxDynamicSharedMemorySize, OL_DSM);

    k_prep<<<816 + 4096, 256>>>(A_log, w_in, w_out, Bw, Cw, x);
    k_mma_in<<<dim3(32, 4, BATCH), 256, MMA_DSM>>>(b_in);
    k_convz<<<dim3(32, 8, BATCH), 256>>>(w_conv, b_conv);
    k_mma_bc<<<256, 256>>>();
    k_scan1<<<dim3(NC, BATCH), 256>>>();
    k_scan2<<<64, 256>>>();
    k_scan3<<<dim3(NC, BATCH), 256>>>(D_skip);
    k_mma_out_ln<<<256, 512, OL_DSM>>>(x, b_out, gamma, beta, out);
}

// round 14
// speedup vs baseline: 1.1021x; 1.0247x over previous
#include <cuda_runtime.h>
#include <cuda_bf16.h>
#include <math.h>
#include <stdint.h>

#define BATCH 4
#define DIMC  256
#define DI    256
#define NS    16
#define NPT   4096
#define NC    64
#define CL    64

// ---- mma.sync + cp.async helpers ----
__device__ __forceinline__ uint32_t smem_u32(const void* p) {
    uint32_t a; asm("{ .reg .u64 t; cvta.to.shared.u64 t, %1; cvt.u32.u64 %0, t; }" : "=r"(a) : "l"(p));
    return a;
}
__device__ __forceinline__ void mma_bf16(float* c, const uint32_t* a, const uint32_t* b) {
    asm volatile(
        "mma.sync.aligned.m16n8k16.row.col.f32.bf16.bf16.f32 "
        "{%0,%1,%2,%3}, {%4,%5,%6,%7}, {%8,%9}, {%0,%1,%2,%3};"
        : "+f"(c[0]), "+f"(c[1]), "+f"(c[2]), "+f"(c[3])
        : "r"(a[0]), "r"(a[1]), "r"(a[2]), "r"(a[3]), "r"(b[0]), "r"(b[1]));
}
__device__ __forceinline__ void ldsm4(uint32_t* r, uint32_t addr) {
    asm volatile("ldmatrix.sync.aligned.m8n8.x4.shared.b16 {%0,%1,%2,%3}, [%4];"
        : "=r"(r[0]), "=r"(r[1]), "=r"(r[2]), "=r"(r[3]) : "r"(addr));
}
__device__ __forceinline__ void ldsm2(uint32_t* r, uint32_t addr) {
    asm volatile("ldmatrix.sync.aligned.m8n8.x2.shared.b16 {%0,%1}, [%2];"
        : "=r"(r[0]), "=r"(r[1]) : "r"(addr));
}
__device__ __forceinline__ void cpa16(uint32_t s, const void* g) {
    asm volatile("cp.async.cg.shared.global [%0], [%1], 16;"
        :: "r"(s), "l"(__cvta_generic_to_global(g)));
}
#define CPA_COMMIT() asm volatile("cp.async.commit_group;" ::: "memory")

// ---------------- scratch (device globals) ----------------
static __device__ float g_xp[BATCH*256*NPT];        // in_proj x1 half [b][d][n]
static __device__ float g_deltaT[BATCH*NPT*DI];
static __device__ float g_Bm[BATCH*NPT*NS];
static __device__ float g_Cm[BATCH*NPT*NS];
static __device__ float g_P[BATCH*NC*NS*DI];
static __device__ float g_H0[BATCH*NC*NS*DI];
static __device__ float g_A[DI*NS];
static __device__ float g_aL[DI*NS];
static __device__ __nv_bfloat16 g_whi[512*256];
static __device__ __nv_bfloat16 g_wlo[512*256];
static __device__ __nv_bfloat16 g_wohi[256*256];
static __device__ __nv_bfloat16 g_wolo[256*256];
static __device__ __nv_bfloat16 g_wbchi[32*256];
static __device__ __nv_bfloat16 g_wbclo[32*256];
static __device__ __nv_bfloat16 g_xthi[BATCH*NPT*DIMC];  // [b][n][c]
static __device__ __nv_bfloat16 g_xtlo[BATCH*NPT*DIMC];
static __device__ __nv_bfloat16 g_xshi[BATCH*NPT*DI];    // silu(conv) [b][n][d]
static __device__ __nv_bfloat16 g_xslo[BATCH*NPT*DI];
static __device__ __nv_bfloat16 g_yhi[BATCH*NPT*DI];     // [b][n][d]
static __device__ __nv_bfloat16 g_ylo[BATCH*NPT*DI];

// ---------------- K-prep ------------------------------------------------------
// x transpose tiles: 64 c x 32 n -> full-sector bfloat162 stores.
__global__ void k_prep(const float* __restrict__ A_log, const float* __restrict__ w_in,
                       const float* __restrict__ w_out, const float* __restrict__ Bw,
                       const float* __restrict__ Cw, const float* __restrict__ x) {
    int blk = blockIdx.x, tid = threadIdx.x;
    if (blk < 512) {
        int i = blk*256 + tid;
        float v = w_in[i];
        __nv_bfloat16 hi = __float2bfloat16(v);
        g_whi[i] = hi;
        g_wlo[i] = __float2bfloat16(v - __bfloat162float(hi));
    } else if (blk < 768) {
        int i = (blk-512)*256 + tid;
        float v = w_out[i];
        __nv_bfloat16 hi = __float2bfloat16(v);
        g_wohi[i] = hi;
        g_wolo[i] = __float2bfloat16(v - __bfloat162float(hi));
    } else if (blk < 784) {
        int i = (blk-768)*256 + tid;
        if (i < DI*NS) {
            float al = A_log[i];
            g_A[i]  = -expf(al);
            g_aL[i] =  expf((float)CL * al);   // CL even
        }
    } else if (blk < 816) {
        int i = (blk-784)*256 + tid;
        float v = (i < 4096) ? Bw[i] : Cw[i - 4096];
        __nv_bfloat16 hi = __float2bfloat16(v);
        g_wbchi[i] = hi;
        g_wbclo[i] = __float2bfloat16(v - __bfloat162float(hi));
    } else {
        __shared__ float s[64][33];
        int t = blk - 816;                 // 0..2047
        int b = t >> 9, rem = t & 511;
        int ct = rem >> 7, nt = rem & 127; // 4 c-tiles x 128 n-tiles
        int c0 = ct*64, n0 = nt*32;
        int tx = tid & 31, ty = tid >> 5;
        #pragma unroll
        for (int i = 0; i < 64; i += 8)
            s[ty+i][tx] = x[((size_t)b*DIMC + c0+ty+i)*NPT + n0 + tx];
        __syncthreads();
        #pragma unroll
        for (int j = 0; j < 4; j++) {
            int n = ty + j*8;
            int c = tx*2;
            float v0 = s[c][n], v1 = s[c+1][n];
            __nv_bfloat16 h0 = __float2bfloat16(v0), h1 = __float2bfloat16(v1);
            __nv_bfloat16 l0 = __float2bfloat16(v0 - __bfloat162float(h0));
            __nv_bfloat16 l1 = __float2bfloat16(v1 - __bfloat162float(h1));
            size_t idx = ((size_t)b*NPT + n0+n)*DIMC + c0 + c;
            __nv_bfloat162 hh; hh.x = h0; hh.y = h1;
            __nv_bfloat162 ll; ll.x = l0; ll.y = l1;
            *(__nv_bfloat162*)&g_xthi[idx] = hh;
            *(__nv_bfloat162*)&g_xtlo[idx] = ll;
        }
    }
}

// ---------------- K1: in_proj mma.sync, cp.async 2-stage pipeline -----------
#define SAS 40
#define ARR_B (128*SAS*2)
#define STG_B (4*ARR_B)
#define MMA_DSM (2*STG_B)
__global__ void __launch_bounds__(256) k_mma_in(const float* __restrict__ bias) {
    extern __shared__ char dsm[];
    uint32_t sb = smem_u32(dsm);
    int tid = threadIdx.x, lane = tid & 31, wid = tid >> 5;
    int wm = wid & 1, wn = wid >> 1;
    int nt = blockIdx.x, mt = blockIdx.y, b = blockIdx.z;
    int o0 = mt*128, n0 = nt*128;

    float acc[4][4][4];
    #pragma unroll
    for (int i = 0; i < 4; i++)
        #pragma unroll
        for (int j = 0; j < 4; j++)
            #pragma unroll
            for (int q = 0; q < 4; q++) acc[i][j][q] = 0.f;

    auto issue = [&](int k, int stg) {
        uint32_t sbase = sb + (uint32_t)stg*STG_B;
        int k0 = k*32;
        #pragma unroll
        for (int i = 0; i < 2; i++) {
            int idx = tid + i*256;
            int row = idx >> 2, seg = idx & 3;
            uint32_t so = (uint32_t)((row*SAS + seg*8)*2);
            size_t ga = (size_t)(o0 + row)*256 + k0 + seg*8;
            size_t gb = ((size_t)b*NPT + n0 + row)*DIMC + k0 + seg*8;
            cpa16(sbase + so,             &g_whi[ga]);
            cpa16(sbase + ARR_B + so,     &g_wlo[ga]);
            cpa16(sbase + 2*ARR_B + so,   &g_xthi[gb]);
            cpa16(sbase + 3*ARR_B + so,   &g_xtlo[gb]);
        }
        CPA_COMMIT();
    };

    uint32_t aoff = (uint32_t)(((wm*64 + (lane&15))*SAS + (lane>>4)*8) * 2);
    uint32_t boff = (uint32_t)(((wn*32 + (lane&7))*SAS + ((lane>>3)&1)*8) * 2);

    issue(0, 0);
    issue(1, 1);

    #pragma unroll
    for (int k = 0; k < 8; k++) {
        if (k < 7) asm volatile("cp.async.wait_group 1;" ::: "memory");
        else       asm volatile("cp.async.wait_group 0;" ::: "memory");
        __syncthreads();
        int stg = k & 1;
        uint32_t aBase = sb + (uint32_t)stg*STG_B + aoff;
        uint32_t bBase = sb + (uint32_t)stg*STG_B + 2*ARR_B + boff;
        #pragma unroll
        for (int ks = 0; ks < 2; ks++) {
            uint32_t koff = ks*32;
            uint32_t ah[4][4], al[4][4], bh[4][2], bl[4][2];
            #pragma unroll
            for (int mi = 0; mi < 4; mi++) {
                ldsm4(ah[mi], aBase + mi*(16*SAS*2) + koff);
                ldsm4(al[mi], aBase + ARR_B + mi*(16*SAS*2) + koff);
            }
            #pragma unroll
            for (int ni = 0; ni < 4; ni++) {
                ldsm2(bh[ni], bBase + ni*(8*SAS*2) + koff);
                ldsm2(bl[ni], bBase + ARR_B + ni*(8*SAS*2) + koff);
            }
            #pragma unroll
            for (int mi = 0; mi < 4; mi++)
                #pragma unroll
                for (int ni = 0; ni < 4; ni++) {
                    mma_bf16(acc[mi][ni], ah[mi], bh[ni]);
                    mma_bf16(acc[mi][ni], ah[mi], bl[ni]);
                    mma_bf16(acc[mi][ni], al[mi], bh[ni]);
                }
        }
        __syncthreads();
        if (k + 2 < 8) issue(k + 2, stg);
    }
    __syncthreads();

    if (mt < 2) {
        #pragma unroll
        for (int mi = 0; mi < 4; mi++) {
            int orow = o0 + wm*64 + mi*16 + (lane>>2);
            float bi0 = bias[orow], bi1 = bias[orow+8];
            #pragma unroll
            for (int ni = 0; ni < 4; ni++) {
                int col = n0 + wn*32 + ni*8 + (lane&3)*2;
                float* d0 = &g_xp[((size_t)b*256 + orow)*NPT + col];
                *(float2*)d0 = make_float2(acc[mi][ni][0] + bi0, acc[mi][ni][1] + bi0);
                *(float2*)(d0 + (size_t)8*NPT) =
                    make_float2(acc[mi][ni][2] + bi1, acc[mi][ni][3] + bi1);
            }
        }
    } else {
        float* stage = (float*)dsm;
        int d0base = (mt - 2) * 128;
        #pragma unroll
        for (int mi = 0; mi < 4; mi++) {
            int rl = wm*64 + mi*16 + (lane>>2);
            float bi0 = bias[o0 + rl], bi1 = bias[o0 + rl + 8];
            #pragma unroll
            for (int ni = 0; ni < 4; ni++) {
                int cl = wn*32 + ni*8 + (lane&3)*2;
                float v0 = acc[mi][ni][0] + bi0, v1 = acc[mi][ni][1] + bi0;
                float v2 = acc[mi][ni][2] + bi1, v3 = acc[mi][ni][3] + bi1;
                stage[(size_t)cl*132 + rl]         = __fdividef(1.f, 1.f + __expf(-v0));
                stage[(size_t)(cl+1)*132 + rl]     = __fdividef(1.f, 1.f + __expf(-v1));
                stage[(size_t)cl*132 + rl + 8]     = __fdividef(1.f, 1.f + __expf(-v2));
                stage[(size_t)(cl+1)*132 + rl + 8] = __fdividef(1.f, 1.f + __expf(-v3));
            }
        }
        __syncthreads();
        for (int idx = tid; idx < 128*128; idx += 256) {
            int n = idx >> 7, dl = idx & 127;
            g_deltaT[((size_t)b*NPT + n0 + n)*DI + d0base + dl] = stage[(size_t)n*132 + dl];
        }
    }
}

// ---------------- K2a: conv+silu -> xs hi/lo bf16 transposed ----------------
#define CZ_P1 133
__global__ void k_convz(const float* __restrict__ wconv, const float* __restrict__ bconv) {
    __shared__ float s1[32*CZ_P1];
    int b = blockIdx.z, dt = blockIdx.y, nt = blockIdx.x;
    int d0 = dt*32, n0 = nt*128;
    int tid = threadIdx.x;
    int tx = tid & 31, ty = tid >> 5;
    const float* xpb = g_xp + (size_t)b*256*NPT;

    for (int r = ty; r < 32; r += 8) {
        const float* src = &xpb[(size_t)(d0+r)*NPT + n0 - 3];
        for (int c = tx; c < 131; c += 32) {
            int n = n0 - 3 + c;
            s1[r*CZ_P1 + c] = (n >= 0) ? src[c] : 0.f;
        }
    }
    __syncthreads();

    int d = d0 + tx;
    float w0 = wconv[d*4+0], w1 = wconv[d*4+1], w2 = wconv[d*4+2], w3 = wconv[d*4+3];
    float bc = bconv[d];
    __nv_bfloat16* xh = g_xshi + ((size_t)b*NPT + n0)*DI + d;
    __nv_bfloat16* xl = g_xslo + ((size_t)b*NPT + n0)*DI + d;
    const float* r1 = &s1[tx*CZ_P1];
    #pragma unroll 4
    for (int n = ty; n < 128; n += 8) {
        float v = fmaf(w3, r1[n+3], fmaf(w2, r1[n+2], fmaf(w1, r1[n+1], fmaf(w0, r1[n], bc))));
        float sv = __fdividef(v, 1.f + __expf(-v));
        __nv_bfloat16 hi = __float2bfloat16(sv);
        xh[(size_t)n*DI] = hi;
        xl[(size_t)n*DI] = __float2bfloat16(sv - __bfloat162float(hi));
    }
}

// ---------------- K2b: B/C projection via mma.sync, 3-stage pipeline --------
#define BC_AB (64*SAS*2)
#define BC_BB (32*SAS*2)
#define BC_STG (2*BC_AB + 2*BC_BB)
__global__ void __launch_bounds__(256) k_mma_bc() {
    __shared__ __align__(16) char dsm[3*BC_STG];
    uint32_t sb = smem_u32(dsm);
    int tid = threadIdx.x, lane = tid & 31, wid = tid >> 5;
    int wm = wid & 3, wn = wid >> 2;
    size_t r0 = (size_t)blockIdx.x * 64;

    float acc[2][4];
    #pragma unroll
    for (int i = 0; i < 2; i++)
        #pragma unroll
        for (int q = 0; q < 4; q++) acc[i][q] = 0.f;

    auto issue = [&](int k, int stg) {
        uint32_t sbase = sb + (uint32_t)stg*BC_STG;
        int k0 = k*32;
        #pragma unroll
        for (int i = 0; i < 2; i++) {
            int idx = tid + i*256;
            int arr = idx >> 8, rem = idx & 255;
            int row = rem >> 2, seg = rem & 3;
            uint32_t so = (uint32_t)arr*BC_AB + (uint32_t)((row*SAS + seg*8)*2);
            size_t g = (r0 + row)*DI + k0 + seg*8;
            cpa16(sbase + so, arr ? (const void*)&g_xslo[g] : (const void*)&g_xshi[g]);
        }
        {
            int arr = tid >> 7, rem = tid & 127;
            int row = rem >> 2, seg = rem & 3;
            uint32_t so = 2*BC_AB + (uint32_t)arr*BC_BB + (uint32_t)((row*SAS + seg*8)*2);
            size_t g = (size_t)row*256 + k0 + seg*8;
            cpa16(sbase + so, arr ? (const void*)&g_wbclo[g] : (const void*)&g_wbchi[g]);
        }
        CPA_COMMIT();
    };

    uint32_t aoff = (uint32_t)(((wm*16 + (lane&15))*SAS + (lane>>4)*8) * 2);
    uint32_t boff = 2*BC_AB + (uint32_t)(((wn*16 + (lane&7))*SAS + ((lane>>3)&1)*8) * 2);

    issue(0, 0);
    issue(1, 1);
    issue(2, 2);

    #pragma unroll
    for (int k = 0; k < 8; k++) {
        if (k < 6)       asm volatile("cp.async.wait_group 2;" ::: "memory");
        else if (k == 6) asm volatile("cp.async.wait_group 1;" ::: "memory");
        else             asm volatile("cp.async.wait_group 0;" ::: "memory");
        __syncthreads();
        int stg = k % 3;
        uint32_t aBase = sb + (uint32_t)stg*BC_STG + aoff;
        uint32_t bBase = sb + (uint32_t)stg*BC_STG + boff;
        #pragma unroll
        for (int ks = 0; ks < 2; ks++) {
            uint32_t koff = ks*32;
            uint32_t ah[4], al[4], bh[2][2], bl[2][2];
            ldsm4(ah, aBase + koff);
            ldsm4(al, aBase + BC_AB + koff);
            #pragma unroll
            for (int ni = 0; ni < 2; ni++) {
                ldsm2(bh[ni], bBase + ni*(8*SAS*2) + koff);
                ldsm2(bl[ni], bBase + BC_BB + ni*(8*SAS*2) + koff);
            }
            #pragma unroll
            for (int ni = 0; ni < 2; ni++) {
                mma_bf16(acc[ni], ah, bh[ni]);
                mma_bf16(acc[ni], ah, bl[ni]);
                mma_bf16(acc[ni], al, bh[ni]);
            }
        }
        __syncthreads();
        if (k + 3 < 8) issue(k + 3, stg);
    }

    #pragma unroll
    for (int ni = 0; ni < 2; ni++) {
        int col = wn*16 + ni*8 + (lane&3)*2;
        float* base = (col < 16) ? g_Bm : g_Cm;
        int cb = col & 15;
        size_t row = r0 + wm*16 + (lane>>2);
        *(float2*)&base[row*NS + cb]     = make_float2(acc[ni][0], acc[ni][1]);
        *(float2*)&base[(row+8)*NS + cb] = make_float2(acc[ni][2], acc[ni][3]);
    }
}

// ---------------- K3 (S1): per-chunk local scan -> P ------------------------
__global__ void k_scan1() {
    __shared__ float sB[CL*NS];
    int b = blockIdx.y, ch = blockIdx.x;
    int tid = threadIdx.x;
    int t0 = ch * CL;
    for (int i = tid; i < CL*NS; i += 256)
        sB[i] = g_Bm[((size_t)b*NPT + t0)*NS + i];
    __syncthreads();
    float A[NS], h[NS];
    #pragma unroll
    for (int s = 0; s < NS; s++) { A[s] = g_A[tid*NS + s]; h[s] = 0.f; }
    const float* dptr = g_deltaT + ((size_t)b*NPT + t0)*DI + tid;
    for (int k = 0; k < CL; k++) {
        float dl = dptr[(size_t)k*DI];
        const float* Bk = &sB[k*NS];
        #pragma unroll
        for (int s = 0; s < NS; s++)
            h[s] = fmaf(A[s], h[s], dl * Bk[s]);
    }
    float* P = g_P + ((size_t)b*NC + ch)*NS*DI + tid;
    #pragma unroll
    for (int s = 0; s < NS; s++) P[s*DI] = h[s];
}

// ---------------- K4 (S2): inter-chunk prefix --------------------------------
__global__ void k_scan2() {
    int g = blockIdx.x * 256 + threadIdx.x;
    int d = g & 255;
    int s = (g >> 8) & 15;
    int b = g >> 12;
    float aL = g_aL[d*NS + s];
    float h = 0.f;
    size_t base = ((size_t)b*NC*NS + s)*DI + d;
    for (int c = 0; c < NC; c++) {
        size_t idx = base + (size_t)c*NS*DI;
        g_H0[idx] = h;
        h = fmaf(aL, h, g_P[idx]);
    }
}

// ---------------- K5 (S3): final scan + y hi/lo bf16 -------------------------
__global__ void k_scan3(const float* __restrict__ Dskip) {
    __shared__ float sB[CL*NS], sC[CL*NS];
    int b = blockIdx.y, ch = blockIdx.x;
    int tid = threadIdx.x;
    int t0 = ch * CL;
    for (int i = tid; i < CL*NS; i += 256) {
        sB[i] = g_Bm[((size_t)b*NPT + t0)*NS + i];
        sC[i] = g_Cm[((size_t)b*NPT + t0)*NS + i];
    }
    __syncthreads();
    float A[NS], h[NS];
    size_t hbase = ((size_t)b*NC + ch)*NS*DI + tid;
    #pragma unroll
    for (int s = 0; s < NS; s++) { A[s] = g_A[tid*NS + s]; h[s] = g_H0[hbase + s*DI]; }
    float dsk = Dskip[tid];
    const float* dptr = g_deltaT + ((size_t)b*NPT + t0)*DI + tid;
    const __nv_bfloat16* xhp = g_xshi + ((size_t)b*NPT + t0)*DI + tid;
    const __nv_bfloat16* xlp = g_xslo + ((size_t)b*NPT + t0)*DI + tid;
    __nv_bfloat16* yh = g_yhi + ((size_t)b*NPT + t0)*DI + tid;
    __nv_bfloat16* yl = g_ylo + ((size_t)b*NPT + t0)*DI + tid;
    for (int k = 0; k < CL; k++) {
        float dl = dptr[(size_t)k*DI];
        float xv = __bfloat162float(xhp[(size_t)k*DI]) + __bfloat162float(xlp[(size_t)k*DI]);
        const float* Bk = &sB[k*NS];
        const float* Ck = &sC[k*NS];
        float y = dsk * xv;
        #pragma unroll
        for (int s = 0; s < NS; s++) {
            h[s] = fmaf(A[s], h[s], dl * Bk[s]);
            y = fmaf(h[s], Ck[s], y);
        }
        __nv_bfloat16 hi = __float2bfloat16(y);
        yh[(size_t)k*DI] = hi;
        yl[(size_t)k*DI] = __float2bfloat16(y - __bfloat162float(hi));
    }
}

// ---------------- K6: fused out_proj + bias + residual + LN + store ----------
#define OL_A_B (128*SAS*2)
#define OL_B_B (256*SAS*2)
#define OL_STG (2*OL_A_B + 2*OL_B_B)
#define OL_DSM (2*OL_STG)
__global__ void __launch_bounds__(512) k_mma_out_ln(
    const float* __restrict__ x, const float* __restrict__ bout,
    const float* __restrict__ gamma, const float* __restrict__ beta,
    float* __restrict__ out) {
    extern __shared__ char dsm[];
    uint32_t sb = smem_u32(dsm);
    int tid = threadIdx.x, lane = tid & 31, wid = tid >> 5;
    int wm = wid & 3, wn = wid >> 2;
    size_t r0 = (size_t)blockIdx.x * 128;
    int b = (int)(r0 >> 12);
    int n0 = (int)(r0 & 4095);

    float acc[2][8][4];
    #pragma unroll
    for (int i = 0; i < 2; i++)
        #pragma unroll
        for (int j = 0; j < 8; j++)
            #pragma unroll
            for (int q = 0; q < 4; q++) acc[i][j][q] = 0.f;

    auto issue = [&](int k, int stg) {
        uint32_t sbase = sb + (uint32_t)stg*OL_STG;
        int k0 = k*32;
        #pragma unroll
        for (int i = 0; i < 2; i++) {
            int idx = tid + i*512;
            int arr = idx >> 9, rem = idx & 511;
            int row = rem >> 2, seg = rem & 3;
            uint32_t so = (uint32_t)arr*OL_A_B + (uint32_t)((row*SAS + seg*8)*2);
            size_t g = (r0 + row)*DI + k0 + seg*8;
            cpa16(sbase + so, arr ? (const void*)&g_ylo[g] : (const void*)&g_yhi[g]);
        }
        #pragma unroll
        for (int i = 0; i < 4; i++) {
            int idx = tid + i*512;
            int arr = idx >> 10, rem = idx & 1023;
            int row = rem >> 2, seg = rem & 3;
            uint32_t so = 2*OL_A_B + (uint32_t)arr*OL_B_B + (uint32_t)((row*SAS + seg*8)*2);
            size_t g = (size_t)row*DI + k0 + seg*8;
            cpa16(sbase + so, arr ? (const void*)&g_wolo[g] : (const void*)&g_wohi[g]);
        }
        CPA_COMMIT();
    };

    uint32_t aoff = (uint32_t)(((wm*32 + (lane&15))*SAS + (lane>>4)*8) * 2);
    uint32_t boff = 2*OL_A_B + (uint32_t)(((wn*64 + (lane&7))*SAS + ((lane>>3)&1)*8) * 2);

    issue(0, 0);
    issue(1, 1);

    #pragma unroll
    for (int k = 0; k < 8; k++) {
        if (k < 7) asm volatile("cp.async.wait_group 1;" ::: "memory");
        else       asm volatile("cp.async.wait_group 0;" ::: "memory");
        __syncthreads();
        int stg = k & 1;
        uint32_t aBase = sb + (uint32_t)stg*OL_STG + aoff;
        uint32_t bBase = sb + (uint32_t)stg*OL_STG + boff;
        #pragma unroll
        for (int ks = 0; ks < 2; ks++) {
            uint32_t koff = ks*32;
            uint32_t ah[2][4], al[2][4], bh[8][2], bl[8][2];
            #pragma unroll
            for (int mi = 0; mi < 2; mi++) {
                ldsm4(ah[mi], aBase + mi*(16*SAS*2) + koff);
                ldsm4(al[mi], aBase + OL_A_B + mi*(16*SAS*2) + koff);
            }
            #pragma unroll
            for (int ni = 0; ni < 8; ni++) {
                ldsm2(bh[ni], bBase + ni*(8*SAS*2) + koff);
                ldsm2(bl[ni], bBase + OL_B_B + ni*(8*SAS*2) + koff);
            }
            #pragma unroll
            for (int mi = 0; mi < 2; mi++)
                #pragma unroll
                for (int ni = 0; ni < 8; ni++) {
                    mma_bf16(acc[mi][ni], ah[mi], bh[ni]);
                    mma_bf16(acc[mi][ni], ah[mi], bl[ni]);
                    mma_bf16(acc[mi][ni], al[mi], bh[ni]);
                }
        }
        __syncthreads();
        if (k + 2 < 8) issue(k + 2, stg);
    }
    __syncthreads();

    float* stage = (float*)dsm;
    float* mu = (float*)(dsm + 256*36*4);
    float* rs = mu + 32;
    for (int p = 0; p < 4; p++) {
        if (wm == p) {
            #pragma unroll
            for (int mi = 0; mi < 2; mi++) {
                int rl = mi*16 + (lane>>2);
                #pragma unroll
                for (int ni = 0; ni < 8; ni++) {
                    int c = wn*64 + ni*8 + (lane&3)*2;
                    float b0 = bout[c], b1 = bout[c+1];
                    stage[(size_t)c*36 + rl]         = acc[mi][ni][0] + b0;
                    stage[(size_t)(c+1)*36 + rl]     = acc[mi][ni][1] + b1;
                    stage[(size_t)c*36 + rl + 8]     = acc[mi][ni][2] + b0;
                    stage[(size_t)(c+1)*36 + rl + 8] = acc[mi][ni][3] + b1;
                }
            }
        }
        __syncthreads();
        int nb = n0 + p*32;
        for (int idx = tid; idx < 8192; idx += 512) {
            int c = idx >> 5, nn = idx & 31;
            stage[(size_t)c*36 + nn] += x[((size_t)b*DIMC + c)*NPT + nb + nn];
        }
        __syncthreads();
        {
            int nn = wid*2 + (lane>>4);
            int h = lane & 15;
            float sum = 0.f, sq = 0.f;
            #pragma unroll
            for (int c = h; c < 256; c += 16) {
                float v = stage[(size_t)c*36 + nn];
                sum += v; sq += v*v;
            }
            #pragma unroll
            for (int o = 1; o < 16; o <<= 1) {
                sum += __shfl_xor_sync(0xFFFFFFFFu, sum, o);
                sq  += __shfl_xor_sync(0xFFFFFFFFu, sq,  o);
            }
            if (h == 0) {
                float m = sum * (1.f/256.f);
                mu[nn] = m;
                rs[nn] = rsqrtf(sq * (1.f/256.f) - m*m + 1e-5f);
            }
        }
        __syncthreads();
        for (int idx = tid; idx < 8192; idx += 512) {
            int c = idx >> 5, nn = idx & 31;
            float v = (stage[(size_t)c*36 + nn] - mu[nn]) * rs[nn] * gamma[c] + beta[c];
            out[((size_t)b*DIMC + c)*NPT + nb + nn] = v;
        }
        __syncthreads();
    }
}

// ---------------- launch ------------------------------------------------------
extern "C" void kernel_launch(void* const* d_in, const int* in_sizes, int n_in,
                              void* d_out, int out_size) {
    const float* x      = (const float*)d_in[0];
    const float* w_in   = (const float*)d_in[1];
    const float* b_in   = (const float*)d_in[2];
    const float* w_conv = (const float*)d_in[3];
    const float* b_conv = (const float*)d_in[4];
    const float* A_log  = (const float*)d_in[5];
    const float* D_skip = (const float*)d_in[6];
    const float* Bw     = (const float*)d_in[7];
    const float* Cw     = (const float*)d_in[8];
    const float* w_out  = (const float*)d_in[9];
    const float* b_out  = (const float*)d_in[10];
    const float* gamma  = (const float*)d_in[11];
    const float* beta   = (const float*)d_in[12];
    float* out = (float*)d_out;

    cudaFuncSetAttribute(k_mma_in,     cudaFuncAttributeMaxDynamicSharedMemorySize, MMA_DSM);
    cudaFuncSetAttribute(k_mma_out_ln, cudaFuncAttributeMaxDynamicSharedMemorySize, OL_DSM);

    k_prep<<<816 + 2048, 256>>>(A_log, w_in, w_out, Bw, Cw, x);
    k_mma_in<<<dim3(32, 4, BATCH), 256, MMA_DSM>>>(b_in);
    k_convz<<<dim3(32, 8, BATCH), 256>>>(w_conv, b_conv);
    k_mma_bc<<<256, 256>>>();
    k_scan1<<<dim3(NC, BATCH), 256>>>();
    k_scan2<<<64, 256>>>();
    k_scan3<<<dim3(NC, BATCH), 256>>>(D_skip);
    k_mma_out_ln<<<128, 512, OL_DSM>>>(x, b_out, gamma, beta, out);
}